// round 1
// baseline (speedup 1.0000x reference)
#include <cuda_runtime.h>
#include <cuda_bf16.h>
#include <math.h>

// ---------------------------------------------------------------------------
// GPT-2 transformer block, fp32 baseline.
// B=2, T=2048, C=768, H=12, hd=64.  M = B*T = 4096.
// ---------------------------------------------------------------------------

#define M_ROWS 4096
#define C_DIM  768
#define C3_DIM 2304
#define C4_DIM 3072
#define N_HEAD 12
#define HD     64
#define T_SEQ  2048

// Scratch (device globals; no runtime allocation allowed).
__device__ float g_h  [M_ROWS * C_DIM];   // ln1 out
__device__ float g_qkv[M_ROWS * C3_DIM];  // qkv
__device__ float g_y  [M_ROWS * C_DIM];   // attention out
__device__ float g_x1 [M_ROWS * C_DIM];   // residual 1
__device__ float g_h2 [M_ROWS * C_DIM];   // ln2 out
__device__ float g_u  [M_ROWS * C4_DIM];  // gelu(fc)

// ---------------------------------------------------------------------------
// LayerNorm: one block per row of 768, 256 threads (3 elements/thread).
// ---------------------------------------------------------------------------
__global__ __launch_bounds__(256) void ln_kernel(
    const float* __restrict__ x, const float* __restrict__ g,
    const float* __restrict__ b, float* __restrict__ out)
{
    int row = blockIdx.x;
    int tid = threadIdx.x;
    const float* xr = x + (size_t)row * C_DIM;

    float v0 = xr[tid];
    float v1 = xr[tid + 256];
    float v2 = xr[tid + 512];

    float s  = v0 + v1 + v2;
    float sq = v0 * v0 + v1 * v1 + v2 * v2;

    #pragma unroll
    for (int o = 16; o > 0; o >>= 1) {
        s  += __shfl_xor_sync(0xffffffffu, s,  o);
        sq += __shfl_xor_sync(0xffffffffu, sq, o);
    }
    __shared__ float ss[8], sqs[8];
    int wid = tid >> 5, lane = tid & 31;
    if (lane == 0) { ss[wid] = s; sqs[wid] = sq; }
    __syncthreads();
    s = 0.f; sq = 0.f;
    #pragma unroll
    for (int i = 0; i < 8; i++) { s += ss[i]; sq += sqs[i]; }

    float mu  = s * (1.0f / C_DIM);
    float var = sq * (1.0f / C_DIM) - mu * mu;
    float inv = rsqrtf(var + 1e-5f);

    float* orow = out + (size_t)row * C_DIM;
    orow[tid]       = (v0 - mu) * inv * g[tid]       + b[tid];
    orow[tid + 256] = (v1 - mu) * inv * g[tid + 256] + b[tid + 256];
    orow[tid + 512] = (v2 - mu) * inv * g[tid + 512] + b[tid + 512];
}

// ---------------------------------------------------------------------------
// SGEMM: C[M,N] = A[M,K] @ B[K,N] + bias, with epilogue:
//   EP=0: bias only      EP=1: bias + residual      EP=2: bias + GELU
// 128x128 tile, BK=8, 256 threads, 8x8 micro-tile. All dims divisible.
// ---------------------------------------------------------------------------
__device__ __forceinline__ float gelu_f(float v) {
    const float c = 0.7978845608028654f;
    float v3 = v * v * v;
    return 0.5f * v * (1.0f + tanhf(c * (v + 0.044715f * v3)));
}

template <int EP>
__global__ __launch_bounds__(256) void sgemm_kernel(
    const float* __restrict__ A, const float* __restrict__ B,
    const float* __restrict__ bias, const float* __restrict__ res,
    float* __restrict__ C, int M, int N, int K)
{
    __shared__ float As[8][128];   // transposed A tile
    __shared__ float Bs[8][128];

    int tid = threadIdx.x;
    int bm = blockIdx.y, bn = blockIdx.x;

    int arow = tid >> 1;            // 0..127
    int acol = (tid & 1) * 4;       // 0 or 4
    int brow = tid >> 5;            // 0..7
    int bcol = (tid & 31) * 4;      // 0..124

    const float* Ab = A + (size_t)(bm * 128) * K;
    const float* Bb = B + bn * 128;

    int tx = tid & 15, ty = tid >> 4;

    float acc[8][8];
    #pragma unroll
    for (int i = 0; i < 8; i++)
        #pragma unroll
        for (int j = 0; j < 8; j++) acc[i][j] = 0.f;

    for (int k0 = 0; k0 < K; k0 += 8) {
        float4 a = *(const float4*)(Ab + (size_t)arow * K + k0 + acol);
        float4 bv = *(const float4*)(Bb + (size_t)(k0 + brow) * N + bcol);
        As[acol + 0][arow] = a.x;
        As[acol + 1][arow] = a.y;
        As[acol + 2][arow] = a.z;
        As[acol + 3][arow] = a.w;
        *(float4*)&Bs[brow][bcol] = bv;
        __syncthreads();

        #pragma unroll
        for (int kk = 0; kk < 8; kk++) {
            float4 a0 = *(const float4*)&As[kk][ty * 8];
            float4 a1 = *(const float4*)&As[kk][ty * 8 + 4];
            float4 b0 = *(const float4*)&Bs[kk][tx * 8];
            float4 b1 = *(const float4*)&Bs[kk][tx * 8 + 4];
            float ar[8] = {a0.x, a0.y, a0.z, a0.w, a1.x, a1.y, a1.z, a1.w};
            float br[8] = {b0.x, b0.y, b0.z, b0.w, b1.x, b1.y, b1.z, b1.w};
            #pragma unroll
            for (int i = 0; i < 8; i++)
                #pragma unroll
                for (int j = 0; j < 8; j++)
                    acc[i][j] = fmaf(ar[i], br[j], acc[i][j]);
        }
        __syncthreads();
    }

    int ccol0 = bn * 128 + tx * 8;
    float4 bi0 = *(const float4*)&bias[ccol0];
    float4 bi1 = *(const float4*)&bias[ccol0 + 4];

    #pragma unroll
    for (int i = 0; i < 8; i++) {
        int crow = bm * 128 + ty * 8 + i;
        float v[8];
        v[0] = acc[i][0] + bi0.x; v[1] = acc[i][1] + bi0.y;
        v[2] = acc[i][2] + bi0.z; v[3] = acc[i][3] + bi0.w;
        v[4] = acc[i][4] + bi1.x; v[5] = acc[i][5] + bi1.y;
        v[6] = acc[i][6] + bi1.z; v[7] = acc[i][7] + bi1.w;
        if (EP == 1) {
            float4 r0 = *(const float4*)&res[(size_t)crow * N + ccol0];
            float4 r1 = *(const float4*)&res[(size_t)crow * N + ccol0 + 4];
            v[0] += r0.x; v[1] += r0.y; v[2] += r0.z; v[3] += r0.w;
            v[4] += r1.x; v[5] += r1.y; v[6] += r1.z; v[7] += r1.w;
        }
        if (EP == 2) {
            #pragma unroll
            for (int j = 0; j < 8; j++) v[j] = gelu_f(v[j]);
        }
        float4 o0 = {v[0], v[1], v[2], v[3]};
        float4 o1 = {v[4], v[5], v[6], v[7]};
        *(float4*)&C[(size_t)crow * N + ccol0]     = o0;
        *(float4*)&C[(size_t)crow * N + ccol0 + 4] = o1;
    }
}

// ---------------------------------------------------------------------------
// Flash attention (causal, fp32). Block = 64-query tile for one (batch, head).
// 128 threads: (row = tid/2) owns one query row; (part = tid&1) owns 32 dims.
// Scores go to Ssm[j][row] (transposed to avoid bank conflicts).
// ---------------------------------------------------------------------------
__global__ __launch_bounds__(128) void attn_kernel(
    const float* __restrict__ qkv, float* __restrict__ y)
{
    __shared__ float Ks[64][64];
    __shared__ float Vs[64][64];
    __shared__ float Ssm[64][64];   // [j][row]

    int qt = blockIdx.x;   // query tile 0..31
    int hh = blockIdx.y;   // head
    int bb = blockIdx.z;   // batch
    int tid = threadIdx.x;
    int row = tid >> 1;
    int part = tid & 1;
    const float scale = 0.125f;   // 1/sqrt(64)

    size_t qbase = ((size_t)(bb * T_SEQ + qt * 64 + row)) * C3_DIM + hh * HD + part * 32;
    float4 qv[8];
    #pragma unroll
    for (int i = 0; i < 8; i++) qv[i] = *(const float4*)(qkv + qbase + i * 4);

    float4 acc[8];
    #pragma unroll
    for (int i = 0; i < 8; i++) acc[i] = make_float4(0.f, 0.f, 0.f, 0.f);
    float m = -1e30f, l = 0.f;

    for (int kt = 0; kt <= qt; kt++) {
        __syncthreads();
        // Load K & V tiles (64x64 each): 1024 float4s, 8 per thread.
        for (int p = tid; p < 1024; p += 128) {
            int r = p >> 4;
            int c4 = (p & 15) << 2;
            size_t gk = ((size_t)(bb * T_SEQ + kt * 64 + r)) * C3_DIM + C_DIM + hh * HD + c4;
            *(float4*)&Ks[r][c4] = *(const float4*)(qkv + gk);
            *(float4*)&Vs[r][c4] = *(const float4*)(qkv + gk + C_DIM);
        }
        __syncthreads();

        bool diag = (kt == qt);
        float mt = -1e30f;
        #pragma unroll 4
        for (int j = 0; j < 64; j++) {
            const float4* kr = (const float4*)&Ks[j][part * 32];
            float s = 0.f;
            #pragma unroll
            for (int i = 0; i < 8; i++) {
                float4 k4 = kr[i];
                s = fmaf(qv[i].x, k4.x, s);
                s = fmaf(qv[i].y, k4.y, s);
                s = fmaf(qv[i].z, k4.z, s);
                s = fmaf(qv[i].w, k4.w, s);
            }
            s += __shfl_xor_sync(0xffffffffu, s, 1);
            s *= scale;
            if (diag && j > row) s = -1e30f;
            if (part == 0) Ssm[j][row] = s;
            mt = fmaxf(mt, s);
        }
        __syncwarp();

        float mn = fmaxf(m, mt);
        float corr = __expf(m - mn);
        m = mn;
        l *= corr;
        #pragma unroll
        for (int i = 0; i < 8; i++) {
            acc[i].x *= corr; acc[i].y *= corr;
            acc[i].z *= corr; acc[i].w *= corr;
        }

        #pragma unroll 2
        for (int j = 0; j < 64; j++) {
            float p = __expf(Ssm[j][row] - m);
            l += p;
            const float4* vr = (const float4*)&Vs[j][part * 32];
            #pragma unroll
            for (int i = 0; i < 8; i++) {
                float4 v4 = vr[i];
                acc[i].x = fmaf(p, v4.x, acc[i].x);
                acc[i].y = fmaf(p, v4.y, acc[i].y);
                acc[i].z = fmaf(p, v4.z, acc[i].z);
                acc[i].w = fmaf(p, v4.w, acc[i].w);
            }
        }
    }

    float inv = 1.0f / l;
    size_t yb = ((size_t)(bb * T_SEQ + qt * 64 + row)) * C_DIM + hh * HD + part * 32;
    #pragma unroll
    for (int i = 0; i < 8; i++) {
        float4 o;
        o.x = acc[i].x * inv; o.y = acc[i].y * inv;
        o.z = acc[i].z * inv; o.w = acc[i].w * inv;
        *(float4*)(y + yb + i * 4) = o;
    }
}

// ---------------------------------------------------------------------------
// Launch
// ---------------------------------------------------------------------------
extern "C" void kernel_launch(void* const* d_in, const int* in_sizes, int n_in,
                              void* d_out, int out_size)
{
    const float* x           = (const float*)d_in[0];
    const float* ln1_g       = (const float*)d_in[1];
    const float* ln1_b       = (const float*)d_in[2];
    const float* w_attn      = (const float*)d_in[3];
    const float* b_attn      = (const float*)d_in[4];
    const float* w_attn_proj = (const float*)d_in[5];
    const float* b_attn_proj = (const float*)d_in[6];
    const float* ln2_g       = (const float*)d_in[7];
    const float* ln2_b       = (const float*)d_in[8];
    const float* w_fc        = (const float*)d_in[9];
    const float* b_fc        = (const float*)d_in[10];
    const float* w_mlp_proj  = (const float*)d_in[11];
    const float* b_mlp_proj  = (const float*)d_in[12];
    float* out = (float*)d_out;

    float *h, *qkv, *y, *x1, *h2, *u;
    cudaGetSymbolAddress((void**)&h,   g_h);
    cudaGetSymbolAddress((void**)&qkv, g_qkv);
    cudaGetSymbolAddress((void**)&y,   g_y);
    cudaGetSymbolAddress((void**)&x1,  g_x1);
    cudaGetSymbolAddress((void**)&h2,  g_h2);
    cudaGetSymbolAddress((void**)&u,   g_u);

    // 1. LN1
    ln_kernel<<<M_ROWS, 256>>>(x, ln1_g, ln1_b, h);
    // 2. qkv = h @ w_attn + b_attn       [4096 x 2304]
    sgemm_kernel<0><<<dim3(C3_DIM / 128, M_ROWS / 128), 256>>>(
        h, w_attn, b_attn, nullptr, qkv, M_ROWS, C3_DIM, C_DIM);
    // 3. attention
    attn_kernel<<<dim3(T_SEQ / 64, N_HEAD, 2), 128>>>(qkv, y);
    // 4. x1 = x + y @ w_attn_proj + b    [4096 x 768]
    sgemm_kernel<1><<<dim3(C_DIM / 128, M_ROWS / 128), 256>>>(
        y, w_attn_proj, b_attn_proj, x, x1, M_ROWS, C_DIM, C_DIM);
    // 5. LN2
    ln_kernel<<<M_ROWS, 256>>>(x1, ln2_g, ln2_b, h2);
    // 6. u = gelu(h2 @ w_fc + b_fc)      [4096 x 3072]
    sgemm_kernel<2><<<dim3(C4_DIM / 128, M_ROWS / 128), 256>>>(
        h2, w_fc, b_fc, nullptr, u, M_ROWS, C4_DIM, C_DIM);
    // 7. out = x1 + u @ w_mlp_proj + b   [4096 x 768]
    sgemm_kernel<1><<<dim3(C_DIM / 128, M_ROWS / 128), 256>>>(
        u, w_mlp_proj, b_mlp_proj, x1, out, M_ROWS, C_DIM, C4_DIM);
}

// round 2
// speedup vs baseline: 2.2725x; 2.2725x over previous
#include <cuda_runtime.h>
#include <cuda_bf16.h>
#include <math.h>

// ---------------------------------------------------------------------------
// GPT-2 transformer block, fp32. Register-tiled flash attention (round 2).
// B=2, T=2048, C=768, H=12, hd=64.  M = B*T = 4096.
// ---------------------------------------------------------------------------

#define M_ROWS 4096
#define C_DIM  768
#define C3_DIM 2304
#define C4_DIM 3072
#define N_HEAD 12
#define HD     64
#define T_SEQ  2048
#define SSTR   68      // smem row stride (floats): 16B-aligned, conflict-padded

// Scratch (device globals; no runtime allocation allowed).
__device__ float g_h  [M_ROWS * C_DIM];   // ln1 out
__device__ float g_qkv[M_ROWS * C3_DIM];  // qkv
__device__ float g_y  [M_ROWS * C_DIM];   // attention out
__device__ float g_x1 [M_ROWS * C_DIM];   // residual 1
__device__ float g_h2 [M_ROWS * C_DIM];   // ln2 out
__device__ float g_u  [M_ROWS * C4_DIM];  // gelu(fc)

// ---------------------------------------------------------------------------
// LayerNorm: one block per row of 768, 256 threads (3 elements/thread).
// ---------------------------------------------------------------------------
__global__ __launch_bounds__(256) void ln_kernel(
    const float* __restrict__ x, const float* __restrict__ g,
    const float* __restrict__ b, float* __restrict__ out)
{
    int row = blockIdx.x;
    int tid = threadIdx.x;
    const float* xr = x + (size_t)row * C_DIM;

    float v0 = xr[tid];
    float v1 = xr[tid + 256];
    float v2 = xr[tid + 512];

    float s  = v0 + v1 + v2;
    float sq = v0 * v0 + v1 * v1 + v2 * v2;

    #pragma unroll
    for (int o = 16; o > 0; o >>= 1) {
        s  += __shfl_xor_sync(0xffffffffu, s,  o);
        sq += __shfl_xor_sync(0xffffffffu, sq, o);
    }
    __shared__ float ss[8], sqs[8];
    int wid = tid >> 5, lane = tid & 31;
    if (lane == 0) { ss[wid] = s; sqs[wid] = sq; }
    __syncthreads();
    s = 0.f; sq = 0.f;
    #pragma unroll
    for (int i = 0; i < 8; i++) { s += ss[i]; sq += sqs[i]; }

    float mu  = s * (1.0f / C_DIM);
    float var = sq * (1.0f / C_DIM) - mu * mu;
    float inv = rsqrtf(var + 1e-5f);

    float* orow = out + (size_t)row * C_DIM;
    orow[tid]       = (v0 - mu) * inv * g[tid]       + b[tid];
    orow[tid + 256] = (v1 - mu) * inv * g[tid + 256] + b[tid + 256];
    orow[tid + 512] = (v2 - mu) * inv * g[tid + 512] + b[tid + 512];
}

// ---------------------------------------------------------------------------
// SGEMM: C[M,N] = A[M,K] @ B[K,N] + bias, with epilogue:
//   EP=0: bias only      EP=1: bias + residual      EP=2: bias + GELU
// 128x128 tile, BK=8, 256 threads, 8x8 micro-tile. All dims divisible.
// ---------------------------------------------------------------------------
__device__ __forceinline__ float gelu_f(float v) {
    const float c = 0.7978845608028654f;
    float v3 = v * v * v;
    return 0.5f * v * (1.0f + tanhf(c * (v + 0.044715f * v3)));
}

template <int EP>
__global__ __launch_bounds__(256) void sgemm_kernel(
    const float* __restrict__ A, const float* __restrict__ B,
    const float* __restrict__ bias, const float* __restrict__ res,
    float* __restrict__ C, int M, int N, int K)
{
    __shared__ float As[8][128];   // transposed A tile
    __shared__ float Bs[8][128];

    int tid = threadIdx.x;
    int bm = blockIdx.y, bn = blockIdx.x;

    int arow = tid >> 1;            // 0..127
    int acol = (tid & 1) * 4;       // 0 or 4
    int brow = tid >> 5;            // 0..7
    int bcol = (tid & 31) * 4;      // 0..124

    const float* Ab = A + (size_t)(bm * 128) * K;
    const float* Bb = B + bn * 128;

    int tx = tid & 15, ty = tid >> 4;

    float acc[8][8];
    #pragma unroll
    for (int i = 0; i < 8; i++)
        #pragma unroll
        for (int j = 0; j < 8; j++) acc[i][j] = 0.f;

    for (int k0 = 0; k0 < K; k0 += 8) {
        float4 a = *(const float4*)(Ab + (size_t)arow * K + k0 + acol);
        float4 bv = *(const float4*)(Bb + (size_t)(k0 + brow) * N + bcol);
        As[acol + 0][arow] = a.x;
        As[acol + 1][arow] = a.y;
        As[acol + 2][arow] = a.z;
        As[acol + 3][arow] = a.w;
        *(float4*)&Bs[brow][bcol] = bv;
        __syncthreads();

        #pragma unroll
        for (int kk = 0; kk < 8; kk++) {
            float4 a0 = *(const float4*)&As[kk][ty * 8];
            float4 a1 = *(const float4*)&As[kk][ty * 8 + 4];
            float4 b0 = *(const float4*)&Bs[kk][tx * 8];
            float4 b1 = *(const float4*)&Bs[kk][tx * 8 + 4];
            float ar[8] = {a0.x, a0.y, a0.z, a0.w, a1.x, a1.y, a1.z, a1.w};
            float br[8] = {b0.x, b0.y, b0.z, b0.w, b1.x, b1.y, b1.z, b1.w};
            #pragma unroll
            for (int i = 0; i < 8; i++)
                #pragma unroll
                for (int j = 0; j < 8; j++)
                    acc[i][j] = fmaf(ar[i], br[j], acc[i][j]);
        }
        __syncthreads();
    }

    int ccol0 = bn * 128 + tx * 8;
    float4 bi0 = *(const float4*)&bias[ccol0];
    float4 bi1 = *(const float4*)&bias[ccol0 + 4];

    #pragma unroll
    for (int i = 0; i < 8; i++) {
        int crow = bm * 128 + ty * 8 + i;
        float v[8];
        v[0] = acc[i][0] + bi0.x; v[1] = acc[i][1] + bi0.y;
        v[2] = acc[i][2] + bi0.z; v[3] = acc[i][3] + bi0.w;
        v[4] = acc[i][4] + bi1.x; v[5] = acc[i][5] + bi1.y;
        v[6] = acc[i][6] + bi1.z; v[7] = acc[i][7] + bi1.w;
        if (EP == 1) {
            float4 r0 = *(const float4*)&res[(size_t)crow * N + ccol0];
            float4 r1 = *(const float4*)&res[(size_t)crow * N + ccol0 + 4];
            v[0] += r0.x; v[1] += r0.y; v[2] += r0.z; v[3] += r0.w;
            v[4] += r1.x; v[5] += r1.y; v[6] += r1.z; v[7] += r1.w;
        }
        if (EP == 2) {
            #pragma unroll
            for (int j = 0; j < 8; j++) v[j] = gelu_f(v[j]);
        }
        float4 o0 = {v[0], v[1], v[2], v[3]};
        float4 o1 = {v[4], v[5], v[6], v[7]};
        *(float4*)&C[(size_t)crow * N + ccol0]     = o0;
        *(float4*)&C[(size_t)crow * N + ccol0 + 4] = o1;
    }
}

// ---------------------------------------------------------------------------
// Flash attention, register-tiled (causal, fp32).
// Block = 64-query tile for one (batch, head). 256 threads as 16x16 grid,
// each thread owns a 4x4 micro-tile of S (and of O).
// S = Q @ K^T via smem outer product (Qs/Ks stored [d][row] transposed),
// softmax on Ps[key][row] (8 rows/warp, 4 lanes/row), then O += P @ V.
// Dynamic smem: 4 * 64*68 + 3*64 floats = 70400 B.
// ---------------------------------------------------------------------------
__global__ __launch_bounds__(256) void attn_kernel(
    const float* __restrict__ qkv, float* __restrict__ y)
{
    extern __shared__ float sm[];
    float* Qs  = sm;                 // [d][row]   stride SSTR
    float* Ks  = Qs + 64 * SSTR;     // [d][key]
    float* Vs  = Ks + 64 * SSTR;     // [key][d]
    float* Ps  = Vs + 64 * SSTR;     // [key][row]
    float* msm = Ps + 64 * SSTR;     // [64] running max
    float* lsm = msm + 64;           // [64] running sum
    float* csm = lsm + 64;           // [64] correction factor

    int qt = blockIdx.x;   // query tile 0..31
    int hh = blockIdx.y;   // head
    int bb = blockIdx.z;   // batch
    int tid = threadIdx.x;
    int tx = tid & 15, ty = tid >> 4;
    int wid = tid >> 5, lane = tid & 31;
    const float scale = 0.125f;   // 1/sqrt(64)

    // Load Q tile (64x64) transposed into Qs[d][row].
    for (int p = tid; p < 1024; p += 256) {
        int r = p >> 4, c4 = (p & 15) << 2;
        float4 v = *(const float4*)(qkv +
            ((size_t)(bb * T_SEQ + qt * 64 + r)) * C3_DIM + hh * HD + c4);
        Qs[(c4 + 0) * SSTR + r] = v.x;
        Qs[(c4 + 1) * SSTR + r] = v.y;
        Qs[(c4 + 2) * SSTR + r] = v.z;
        Qs[(c4 + 3) * SSTR + r] = v.w;
    }
    if (tid < 64) { msm[tid] = -1e30f; lsm[tid] = 0.f; }

    float oacc[4][4];
    #pragma unroll
    for (int i = 0; i < 4; i++)
        #pragma unroll
        for (int j = 0; j < 4; j++) oacc[i][j] = 0.f;

    for (int kt = 0; kt <= qt; kt++) {
        __syncthreads();   // previous iteration done with Ks/Vs/Ps
        // Load K (transposed) and V (natural) tiles.
        for (int p = tid; p < 1024; p += 256) {
            int r = p >> 4, c4 = (p & 15) << 2;
            size_t gk = ((size_t)(bb * T_SEQ + kt * 64 + r)) * C3_DIM
                        + C_DIM + hh * HD + c4;
            float4 kv = *(const float4*)(qkv + gk);
            float4 vv = *(const float4*)(qkv + gk + C_DIM);
            Ks[(c4 + 0) * SSTR + r] = kv.x;
            Ks[(c4 + 1) * SSTR + r] = kv.y;
            Ks[(c4 + 2) * SSTR + r] = kv.z;
            Ks[(c4 + 3) * SSTR + r] = kv.w;
            *(float4*)&Vs[r * SSTR + c4] = vv;
        }
        __syncthreads();

        // S = Q @ K^T  (4x4 per thread, contraction over d)
        float sacc[4][4];
        #pragma unroll
        for (int i = 0; i < 4; i++)
            #pragma unroll
            for (int j = 0; j < 4; j++) sacc[i][j] = 0.f;

        #pragma unroll 8
        for (int d = 0; d < 64; d++) {
            float4 a = *(const float4*)&Qs[d * SSTR + ty * 4];
            float4 b = *(const float4*)&Ks[d * SSTR + tx * 4];
            float ar[4] = {a.x, a.y, a.z, a.w};
            float br[4] = {b.x, b.y, b.z, b.w};
            #pragma unroll
            for (int i = 0; i < 4; i++)
                #pragma unroll
                for (int j = 0; j < 4; j++)
                    sacc[i][j] = fmaf(ar[i], br[j], sacc[i][j]);
        }

        // Scale, causal mask, stage transposed into Ps[key][row].
        bool diag = (kt == qt);
        #pragma unroll
        for (int i = 0; i < 4; i++) {
            #pragma unroll
            for (int j = 0; j < 4; j++) {
                float s = sacc[i][j] * scale;
                if (diag && (tx * 4 + j) > (ty * 4 + i)) s = -1e30f;
                Ps[(tx * 4 + j) * SSTR + (ty * 4 + i)] = s;
            }
        }
        __syncthreads();

        // Online softmax: warp handles 8 rows; 4 lanes per row over 64 keys.
        {
            int row = wid * 8 + (lane >> 2);
            int sub = lane & 3;
            float sv[16];
            float mt = -1e30f;
            #pragma unroll
            for (int c = 0; c < 16; c++) {
                sv[c] = Ps[(sub + c * 4) * SSTR + row];
                mt = fmaxf(mt, sv[c]);
            }
            mt = fmaxf(mt, __shfl_xor_sync(0xffffffffu, mt, 1));
            mt = fmaxf(mt, __shfl_xor_sync(0xffffffffu, mt, 2));
            float mold = msm[row];
            float mnew = fmaxf(mold, mt);
            float psum = 0.f;
            #pragma unroll
            for (int c = 0; c < 16; c++) {
                float p = __expf(sv[c] - mnew);
                psum += p;
                Ps[(sub + c * 4) * SSTR + row] = p;
            }
            psum += __shfl_xor_sync(0xffffffffu, psum, 1);
            psum += __shfl_xor_sync(0xffffffffu, psum, 2);
            if (sub == 0) {
                float corr = __expf(mold - mnew);
                msm[row] = mnew;
                lsm[row] = lsm[row] * corr + psum;
                csm[row] = corr;
            }
        }
        __syncthreads();

        // Rescale O and accumulate O += P @ V (contraction over key).
        float cr[4];
        #pragma unroll
        for (int i = 0; i < 4; i++) cr[i] = csm[ty * 4 + i];
        #pragma unroll
        for (int i = 0; i < 4; i++)
            #pragma unroll
            for (int j = 0; j < 4; j++) oacc[i][j] *= cr[i];

        #pragma unroll 8
        for (int k = 0; k < 64; k++) {
            float4 a = *(const float4*)&Ps[k * SSTR + ty * 4];
            float4 b = *(const float4*)&Vs[k * SSTR + tx * 4];
            float ar[4] = {a.x, a.y, a.z, a.w};
            float br[4] = {b.x, b.y, b.z, b.w};
            #pragma unroll
            for (int i = 0; i < 4; i++)
                #pragma unroll
                for (int j = 0; j < 4; j++)
                    oacc[i][j] = fmaf(ar[i], br[j], oacc[i][j]);
        }
    }

    // Epilogue: normalize rows and write out.
    float inv[4];
    #pragma unroll
    for (int i = 0; i < 4; i++) inv[i] = 1.0f / lsm[ty * 4 + i];
    #pragma unroll
    for (int i = 0; i < 4; i++) {
        size_t yb = ((size_t)(bb * T_SEQ + qt * 64 + ty * 4 + i)) * C_DIM
                    + hh * HD + tx * 4;
        float4 o = {oacc[i][0] * inv[i], oacc[i][1] * inv[i],
                    oacc[i][2] * inv[i], oacc[i][3] * inv[i]};
        *(float4*)(y + yb) = o;
    }
}

#define ATTN_SMEM (size_t)((4 * 64 * SSTR + 3 * 64) * sizeof(float))

// ---------------------------------------------------------------------------
// Launch
// ---------------------------------------------------------------------------
extern "C" void kernel_launch(void* const* d_in, const int* in_sizes, int n_in,
                              void* d_out, int out_size)
{
    const float* x           = (const float*)d_in[0];
    const float* ln1_g       = (const float*)d_in[1];
    const float* ln1_b       = (const float*)d_in[2];
    const float* w_attn      = (const float*)d_in[3];
    const float* b_attn      = (const float*)d_in[4];
    const float* w_attn_proj = (const float*)d_in[5];
    const float* b_attn_proj = (const float*)d_in[6];
    const float* ln2_g       = (const float*)d_in[7];
    const float* ln2_b       = (const float*)d_in[8];
    const float* w_fc        = (const float*)d_in[9];
    const float* b_fc        = (const float*)d_in[10];
    const float* w_mlp_proj  = (const float*)d_in[11];
    const float* b_mlp_proj  = (const float*)d_in[12];
    float* out = (float*)d_out;

    float *h, *qkv, *y, *x1, *h2, *u;
    cudaGetSymbolAddress((void**)&h,   g_h);
    cudaGetSymbolAddress((void**)&qkv, g_qkv);
    cudaGetSymbolAddress((void**)&y,   g_y);
    cudaGetSymbolAddress((void**)&x1,  g_x1);
    cudaGetSymbolAddress((void**)&h2,  g_h2);
    cudaGetSymbolAddress((void**)&u,   g_u);

    cudaFuncSetAttribute(attn_kernel,
        cudaFuncAttributeMaxDynamicSharedMemorySize, (int)ATTN_SMEM);

    // 1. LN1
    ln_kernel<<<M_ROWS, 256>>>(x, ln1_g, ln1_b, h);
    // 2. qkv = h @ w_attn + b_attn       [4096 x 2304]
    sgemm_kernel<0><<<dim3(C3_DIM / 128, M_ROWS / 128), 256>>>(
        h, w_attn, b_attn, nullptr, qkv, M_ROWS, C3_DIM, C_DIM);
    // 3. attention (register-tiled flash)
    attn_kernel<<<dim3(T_SEQ / 64, N_HEAD, 2), 256, ATTN_SMEM>>>(qkv, y);
    // 4. x1 = x + y @ w_attn_proj + b    [4096 x 768]
    sgemm_kernel<1><<<dim3(C_DIM / 128, M_ROWS / 128), 256>>>(
        y, w_attn_proj, b_attn_proj, x, x1, M_ROWS, C_DIM, C_DIM);
    // 5. LN2
    ln_kernel<<<M_ROWS, 256>>>(x1, ln2_g, ln2_b, h2);
    // 6. u = gelu(h2 @ w_fc + b_fc)      [4096 x 3072]
    sgemm_kernel<2><<<dim3(C4_DIM / 128, M_ROWS / 128), 256>>>(
        h2, w_fc, b_fc, nullptr, u, M_ROWS, C4_DIM, C_DIM);
    // 7. out = x1 + u @ w_mlp_proj + b   [4096 x 768]
    sgemm_kernel<1><<<dim3(C_DIM / 128, M_ROWS / 128), 256>>>(
        u, w_mlp_proj, b_mlp_proj, x1, out, M_ROWS, C_DIM, C4_DIM);
}

// round 6
// speedup vs baseline: 3.6754x; 1.6173x over previous
#include <cuda_runtime.h>
#include <cuda_bf16.h>
#include <math.h>
#include <stdint.h>

// ---------------------------------------------------------------------------
// GPT-2 transformer block. GEMMs via mma.sync bf16 (hi/lo split, 3 terms),
// fp32 register-tiled flash attention.
// B=2, T=2048, C=768, H=12, hd=64.  M = B*T = 4096.
// ---------------------------------------------------------------------------

#define M_ROWS 4096
#define C_DIM  768
#define C3_DIM 2304
#define C4_DIM 3072
#define N_HEAD 12
#define HD     64
#define T_SEQ  2048
#define SSTR   68

// ---------------- scratch (device globals) ----------------
__device__ float g_qkv[M_ROWS * C3_DIM];
__device__ float g_x1 [M_ROWS * C_DIM];
__device__ __nv_bfloat16 g_hh [M_ROWS * C_DIM],  g_hl [M_ROWS * C_DIM];
__device__ __nv_bfloat16 g_yh [M_ROWS * C_DIM],  g_yl [M_ROWS * C_DIM];
__device__ __nv_bfloat16 g_h2h[M_ROWS * C_DIM],  g_h2l[M_ROWS * C_DIM];
__device__ __nv_bfloat16 g_uh [M_ROWS * C4_DIM], g_ul [M_ROWS * C4_DIM];
__device__ __nv_bfloat16 g_wqh[C3_DIM * C_DIM],  g_wql[C3_DIM * C_DIM];
__device__ __nv_bfloat16 g_wph[C_DIM * C_DIM],   g_wpl[C_DIM * C_DIM];
__device__ __nv_bfloat16 g_wfh[C4_DIM * C_DIM],  g_wfl[C4_DIM * C_DIM];
__device__ __nv_bfloat16 g_wmh[C_DIM * C4_DIM],  g_wml[C_DIM * C4_DIM];

// ---------------- PTX helpers (base ISA only; no sm_103a features) ----------
__device__ __forceinline__ uint32_t smem_u32(const void* p) {
    uint32_t a;
    asm("{ .reg .u64 t; cvta.to.shared.u64 t, %1; cvt.u32.u64 %0, t; }"
        : "=r"(a) : "l"(p));
    return a;
}

#define CPA16(dst, src) \
    asm volatile("cp.async.cg.shared.global [%0], [%1], 16;" :: "r"(dst), "l"(src))
#define CP_COMMIT() asm volatile("cp.async.commit_group;" ::: "memory")
#define CP_WAIT1()  asm volatile("cp.async.wait_group 1;" ::: "memory")
#define CP_WAIT0()  asm volatile("cp.async.wait_group 0;" ::: "memory")

#define LDSM_X4(r, addr)                                                       \
    asm volatile("ldmatrix.sync.aligned.m8n8.x4.shared.b16 {%0,%1,%2,%3}, [%4];" \
        : "=r"((r)[0]), "=r"((r)[1]), "=r"((r)[2]), "=r"((r)[3]) : "r"(addr))

#define MMA_BF16(d, a, b)                                                      \
    asm volatile("mma.sync.aligned.m16n8k16.row.col.f32.bf16.bf16.f32 "        \
        "{%0,%1,%2,%3}, {%4,%5,%6,%7}, {%8,%9}, {%0,%1,%2,%3};"                \
        : "+f"((d)[0]), "+f"((d)[1]), "+f"((d)[2]), "+f"((d)[3])               \
        : "r"((a)[0]), "r"((a)[1]), "r"((a)[2]), "r"((a)[3]),                  \
          "r"((b)[0]), "r"((b)[1]))

__device__ __forceinline__ float gelu_f(float v) {
    const float c = 0.7978845608028654f;
    return 0.5f * v * (1.0f + tanhf(c * (v + 0.044715f * v * v * v)));
}
__device__ __forceinline__ void split_bf16(float v, __nv_bfloat16& hi, __nv_bfloat16& lo) {
    hi = __float2bfloat16(v);
    lo = __float2bfloat16(v - __bfloat162float(hi));
}

// ---------------------------------------------------------------------------
// mma.sync GEMM: D[M,N] = (Ah+Al)[M,K] @ (Bh+Bl)[N,K]^T  (3 split terms)
// 128x128 CTA tile, 8 warps each 32(M)x64(N), K-chunks of 32, double-buffered
// cp.async. smem stride 40 bf16 (80B) -> conflict-free ldmatrix.
// EP: 0=bias->f32  1/3=bias+res->f32  2=bias+gelu->bf16 hi/lo
// ---------------------------------------------------------------------------
template <int EP>
__global__ __launch_bounds__(256)
void mm_kernel(const __nv_bfloat16* __restrict__ Ah, const __nv_bfloat16* __restrict__ Al,
               const __nv_bfloat16* __restrict__ Bh, const __nv_bfloat16* __restrict__ Bl,
               const float* __restrict__ bias, const float* __restrict__ res,
               float* __restrict__ outF,
               __nv_bfloat16* __restrict__ outH, __nv_bfloat16* __restrict__ outL,
               int M, int N, int K)
{
    __shared__ __nv_bfloat16 Asm[2][128][40];
    __shared__ __nv_bfloat16 Bsm[2][128][40];

    int tid = threadIdx.x;
    int wid = tid >> 5, lane = tid & 31;
    int wm = wid & 3, wn = wid >> 2;        // warp: rows wm*32.., cols wn*64..
    int bm = blockIdx.y, bn = blockIdx.x;

    const int KC  = K / 32;
    const int NIT = 3 * KC;                 // term 0: Ah*Bh, 1: Ah*Bl, 2: Al*Bh

    uint32_t sA[2] = { smem_u32(&Asm[0][0][0]), smem_u32(&Asm[1][0][0]) };
    uint32_t sB[2] = { smem_u32(&Bsm[0][0][0]), smem_u32(&Bsm[1][0][0]) };

    auto load_chunk = [&](int it2, int b2) {
        int term = it2 / KC;
        int k0 = (it2 - term * KC) * 32;
        const __nv_bfloat16* Ag = (term == 2) ? Al : Ah;
        const __nv_bfloat16* Bg = (term == 1) ? Bl : Bh;
        #pragma unroll
        for (int i = 0; i < 2; i++) {
            int s = tid + i * 256;          // 0..511
            int r = s >> 2, c = s & 3;      // row 0..127, 16B col 0..3
            CPA16(sA[b2] + r * 80 + c * 16,
                  (const char*)(Ag + (size_t)(bm * 128 + r) * K + k0) + c * 16);
            CPA16(sB[b2] + r * 80 + c * 16,
                  (const char*)(Bg + (size_t)(bn * 128 + r) * K + k0) + c * 16);
        }
    };

    float acc[2][8][4];
    #pragma unroll
    for (int i = 0; i < 2; i++)
        #pragma unroll
        for (int j = 0; j < 8; j++)
            #pragma unroll
            for (int q = 0; q < 4; q++) acc[i][j][q] = 0.f;

    load_chunk(0, 0); CP_COMMIT();
    load_chunk(1, 1); CP_COMMIT();

    // ldmatrix lane -> (row-within-16, col-8-group)
    int mrow = (lane & 7) + ((lane >> 3) & 1) * 8;
    int kgrp = (lane >> 4) * 8;

    for (int it = 0; it < NIT; ++it) {
        int b = it & 1;
        if (it + 1 < NIT) CP_WAIT1(); else CP_WAIT0();
        __syncthreads();

        #pragma unroll
        for (int ks = 0; ks < 2; ks++) {
            int kcol = ks * 16 + kgrp;
            uint32_t af[2][4], bf[4][4];
            #pragma unroll
            for (int mt = 0; mt < 2; mt++)
                LDSM_X4(af[mt], sA[b] + (wm * 32 + mt * 16 + mrow) * 80 + kcol * 2);
            #pragma unroll
            for (int np = 0; np < 4; np++)
                LDSM_X4(bf[np], sB[b] + (wn * 64 + np * 16 + mrow) * 80 + kcol * 2);
            #pragma unroll
            for (int mt = 0; mt < 2; mt++)
                #pragma unroll
                for (int nt = 0; nt < 8; nt++) {
                    uint32_t bb[2] = { bf[nt >> 1][nt & 1], bf[nt >> 1][(nt & 1) + 2] };
                    MMA_BF16(acc[mt][nt], af[mt], bb);
                }
        }
        __syncthreads();
        if (it + 2 < NIT) { load_chunk(it + 2, b); CP_COMMIT(); }
    }

    // ---- epilogue ----
    #pragma unroll
    for (int mt = 0; mt < 2; mt++) {
        int gr0 = bm * 128 + wm * 32 + mt * 16 + (lane >> 2);
        #pragma unroll
        for (int nt = 0; nt < 8; nt++) {
            int gc = bn * 128 + wn * 64 + nt * 8 + (lane & 3) * 2;
            float2 bi = *(const float2*)(bias + gc);
            #pragma unroll
            for (int h = 0; h < 2; h++) {
                int gr = gr0 + h * 8;
                float v0 = acc[mt][nt][h * 2 + 0] + bi.x;
                float v1 = acc[mt][nt][h * 2 + 1] + bi.y;
                size_t o = (size_t)gr * N + gc;
                if (EP == 1 || EP == 3) {
                    float2 rr = *(const float2*)(res + o);
                    v0 += rr.x; v1 += rr.y;
                }
                if (EP == 2) {
                    v0 = gelu_f(v0); v1 = gelu_f(v1);
                    __nv_bfloat16 h0, h1, l0, l1;
                    split_bf16(v0, h0, l0); split_bf16(v1, h1, l1);
                    *(__nv_bfloat162*)(outH + o) = __nv_bfloat162(h0, h1);
                    *(__nv_bfloat162*)(outL + o) = __nv_bfloat162(l0, l1);
                } else {
                    float2 ov = {v0, v1};
                    *(float2*)(outF + o) = ov;
                }
            }
        }
    }
}

// ---------------------------------------------------------------------------
// Transpose + hi/lo split:  w[K,N] f32 -> th/tl [N,K] bf16
// ---------------------------------------------------------------------------
__global__ __launch_bounds__(256) void tsplit_kernel(
    const float* __restrict__ w, __nv_bfloat16* __restrict__ th,
    __nv_bfloat16* __restrict__ tl, int K, int N)
{
    __shared__ float t[32][33];
    int n0 = blockIdx.x * 32, k0 = blockIdx.y * 32;
    int tx = threadIdx.x & 31, ty = threadIdx.x >> 5;  // 32 x 8
    #pragma unroll
    for (int j = 0; j < 4; j++) {
        int k = ty + j * 8;
        t[k][tx] = w[(size_t)(k0 + k) * N + n0 + tx];
    }
    __syncthreads();
    #pragma unroll
    for (int j = 0; j < 4; j++) {
        int nn = ty + j * 8;
        float v = t[tx][nn];
        __nv_bfloat16 hi, lo;
        split_bf16(v, hi, lo);
        size_t o = (size_t)(n0 + nn) * K + k0 + tx;
        th[o] = hi; tl[o] = lo;
    }
}

// ---------------------------------------------------------------------------
// LayerNorm -> bf16 hi/lo
// ---------------------------------------------------------------------------
__global__ __launch_bounds__(256) void ln_split_kernel(
    const float* __restrict__ x, const float* __restrict__ g,
    const float* __restrict__ b, __nv_bfloat16* __restrict__ oh,
    __nv_bfloat16* __restrict__ ol)
{
    int row = blockIdx.x;
    int tid = threadIdx.x;
    const float* xr = x + (size_t)row * C_DIM;

    float v0 = xr[tid], v1 = xr[tid + 256], v2 = xr[tid + 512];
    float s = v0 + v1 + v2;
    float sq = v0 * v0 + v1 * v1 + v2 * v2;
    #pragma unroll
    for (int o = 16; o > 0; o >>= 1) {
        s  += __shfl_xor_sync(0xffffffffu, s,  o);
        sq += __shfl_xor_sync(0xffffffffu, sq, o);
    }
    __shared__ float ss[8], sqs[8];
    int wid = tid >> 5, lane = tid & 31;
    if (lane == 0) { ss[wid] = s; sqs[wid] = sq; }
    __syncthreads();
    s = 0.f; sq = 0.f;
    #pragma unroll
    for (int i = 0; i < 8; i++) { s += ss[i]; sq += sqs[i]; }

    float mu = s * (1.0f / C_DIM);
    float var = sq * (1.0f / C_DIM) - mu * mu;
    float inv = rsqrtf(var + 1e-5f);

    size_t base = (size_t)row * C_DIM;
    #pragma unroll
    for (int e = 0; e < 3; e++) {
        int idx = tid + e * 256;
        float val = ((e == 0 ? v0 : e == 1 ? v1 : v2) - mu) * inv * g[idx] + b[idx];
        __nv_bfloat16 hi, lo;
        split_bf16(val, hi, lo);
        oh[base + idx] = hi; ol[base + idx] = lo;
    }
}

// ---------------------------------------------------------------------------
// Flash attention, register-tiled (causal, fp32), outputs bf16 hi/lo.
// ---------------------------------------------------------------------------
__global__ __launch_bounds__(256) void attn_kernel(
    const float* __restrict__ qkv,
    __nv_bfloat16* __restrict__ yh, __nv_bfloat16* __restrict__ yl)
{
    extern __shared__ float sm[];
    float* Qs  = sm;
    float* Ks  = Qs + 64 * SSTR;
    float* Vs  = Ks + 64 * SSTR;
    float* Ps  = Vs + 64 * SSTR;
    float* msm = Ps + 64 * SSTR;
    float* lsm = msm + 64;
    float* csm = lsm + 64;

    int qt = blockIdx.x, hh = blockIdx.y, bb = blockIdx.z;
    int tid = threadIdx.x;
    int tx = tid & 15, ty = tid >> 4;
    int wid = tid >> 5, lane = tid & 31;
    const float scale = 0.125f;

    for (int p = tid; p < 1024; p += 256) {
        int r = p >> 4, c4 = (p & 15) << 2;
        float4 v = *(const float4*)(qkv +
            ((size_t)(bb * T_SEQ + qt * 64 + r)) * C3_DIM + hh * HD + c4);
        Qs[(c4 + 0) * SSTR + r] = v.x;
        Qs[(c4 + 1) * SSTR + r] = v.y;
        Qs[(c4 + 2) * SSTR + r] = v.z;
        Qs[(c4 + 3) * SSTR + r] = v.w;
    }
    if (tid < 64) { msm[tid] = -1e30f; lsm[tid] = 0.f; }

    float oacc[4][4];
    #pragma unroll
    for (int i = 0; i < 4; i++)
        #pragma unroll
        for (int j = 0; j < 4; j++) oacc[i][j] = 0.f;

    for (int kt = 0; kt <= qt; kt++) {
        __syncthreads();
        for (int p = tid; p < 1024; p += 256) {
            int r = p >> 4, c4 = (p & 15) << 2;
            size_t gk = ((size_t)(bb * T_SEQ + kt * 64 + r)) * C3_DIM
                        + C_DIM + hh * HD + c4;
            float4 kv = *(const float4*)(qkv + gk);
            float4 vv = *(const float4*)(qkv + gk + C_DIM);
            Ks[(c4 + 0) * SSTR + r] = kv.x;
            Ks[(c4 + 1) * SSTR + r] = kv.y;
            Ks[(c4 + 2) * SSTR + r] = kv.z;
            Ks[(c4 + 3) * SSTR + r] = kv.w;
            *(float4*)&Vs[r * SSTR + c4] = vv;
        }
        __syncthreads();

        float sacc[4][4];
        #pragma unroll
        for (int i = 0; i < 4; i++)
            #pragma unroll
            for (int j = 0; j < 4; j++) sacc[i][j] = 0.f;

        #pragma unroll 8
        for (int d = 0; d < 64; d++) {
            float4 a = *(const float4*)&Qs[d * SSTR + ty * 4];
            float4 b = *(const float4*)&Ks[d * SSTR + tx * 4];
            float ar[4] = {a.x, a.y, a.z, a.w};
            float br[4] = {b.x, b.y, b.z, b.w};
            #pragma unroll
            for (int i = 0; i < 4; i++)
                #pragma unroll
                for (int j = 0; j < 4; j++)
                    sacc[i][j] = fmaf(ar[i], br[j], sacc[i][j]);
        }

        bool diag = (kt == qt);
        #pragma unroll
        for (int i = 0; i < 4; i++)
            #pragma unroll
            for (int j = 0; j < 4; j++) {
                float s = sacc[i][j] * scale;
                if (diag && (tx * 4 + j) > (ty * 4 + i)) s = -1e30f;
                Ps[(tx * 4 + j) * SSTR + (ty * 4 + i)] = s;
            }
        __syncthreads();

        {
            int row = wid * 8 + (lane >> 2);
            int sub = lane & 3;
            float sv[16];
            float mt = -1e30f;
            #pragma unroll
            for (int c = 0; c < 16; c++) {
                sv[c] = Ps[(sub + c * 4) * SSTR + row];
                mt = fmaxf(mt, sv[c]);
            }
            mt = fmaxf(mt, __shfl_xor_sync(0xffffffffu, mt, 1));
            mt = fmaxf(mt, __shfl_xor_sync(0xffffffffu, mt, 2));
            float mold = msm[row];
            float mnew = fmaxf(mold, mt);
            float psum = 0.f;
            #pragma unroll
            for (int c = 0; c < 16; c++) {
                float p = __expf(sv[c] - mnew);
                psum += p;
                Ps[(sub + c * 4) * SSTR + row] = p;
            }
            psum += __shfl_xor_sync(0xffffffffu, psum, 1);
            psum += __shfl_xor_sync(0xffffffffu, psum, 2);
            if (sub == 0) {
                float corr = __expf(mold - mnew);
                msm[row] = mnew;
                lsm[row] = lsm[row] * corr + psum;
                csm[row] = corr;
            }
        }
        __syncthreads();

        float cr[4];
        #pragma unroll
        for (int i = 0; i < 4; i++) cr[i] = csm[ty * 4 + i];
        #pragma unroll
        for (int i = 0; i < 4; i++)
            #pragma unroll
            for (int j = 0; j < 4; j++) oacc[i][j] *= cr[i];

        #pragma unroll 8
        for (int k = 0; k < 64; k++) {
            float4 a = *(const float4*)&Ps[k * SSTR + ty * 4];
            float4 b = *(const float4*)&Vs[k * SSTR + tx * 4];
            float ar[4] = {a.x, a.y, a.z, a.w};
            float br[4] = {b.x, b.y, b.z, b.w};
            #pragma unroll
            for (int i = 0; i < 4; i++)
                #pragma unroll
                for (int j = 0; j < 4; j++)
                    oacc[i][j] = fmaf(ar[i], br[j], oacc[i][j]);
        }
    }

    float inv[4];
    #pragma unroll
    for (int i = 0; i < 4; i++) inv[i] = 1.0f / lsm[ty * 4 + i];
    #pragma unroll
    for (int i = 0; i < 4; i++) {
        size_t yb = ((size_t)(bb * T_SEQ + qt * 64 + ty * 4 + i)) * C_DIM
                    + hh * HD + tx * 4;
        float v0 = oacc[i][0] * inv[i], v1 = oacc[i][1] * inv[i];
        float v2 = oacc[i][2] * inv[i], v3 = oacc[i][3] * inv[i];
        __nv_bfloat16 h0, h1, h2, h3, l0, l1, l2, l3;
        split_bf16(v0, h0, l0); split_bf16(v1, h1, l1);
        split_bf16(v2, h2, l2); split_bf16(v3, h3, l3);
        *(__nv_bfloat162*)(yh + yb)     = __nv_bfloat162(h0, h1);
        *(__nv_bfloat162*)(yh + yb + 2) = __nv_bfloat162(h2, h3);
        *(__nv_bfloat162*)(yl + yb)     = __nv_bfloat162(l0, l1);
        *(__nv_bfloat162*)(yl + yb + 2) = __nv_bfloat162(l2, l3);
    }
}

#define ATTN_SMEM (size_t)((4 * 64 * SSTR + 3 * 64) * sizeof(float))

// ---------------------------------------------------------------------------
// Launch
// ---------------------------------------------------------------------------
extern "C" void kernel_launch(void* const* d_in, const int* in_sizes, int n_in,
                              void* d_out, int out_size)
{
    const float* x           = (const float*)d_in[0];
    const float* ln1_g       = (const float*)d_in[1];
    const float* ln1_b       = (const float*)d_in[2];
    const float* w_attn      = (const float*)d_in[3];
    const float* b_attn      = (const float*)d_in[4];
    const float* w_attn_proj = (const float*)d_in[5];
    const float* b_attn_proj = (const float*)d_in[6];
    const float* ln2_g       = (const float*)d_in[7];
    const float* ln2_b       = (const float*)d_in[8];
    const float* w_fc        = (const float*)d_in[9];
    const float* b_fc        = (const float*)d_in[10];
    const float* w_mlp_proj  = (const float*)d_in[11];
    const float* b_mlp_proj  = (const float*)d_in[12];
    float* out = (float*)d_out;

    float *qkv, *x1;
    __nv_bfloat16 *hh, *hl, *yh, *yl, *h2h, *h2l, *uh, *ul;
    __nv_bfloat16 *wqh, *wql, *wph, *wpl, *wfh, *wfl, *wmh, *wml;
    cudaGetSymbolAddress((void**)&qkv, g_qkv);
    cudaGetSymbolAddress((void**)&x1,  g_x1);
    cudaGetSymbolAddress((void**)&hh,  g_hh);  cudaGetSymbolAddress((void**)&hl,  g_hl);
    cudaGetSymbolAddress((void**)&yh,  g_yh);  cudaGetSymbolAddress((void**)&yl,  g_yl);
    cudaGetSymbolAddress((void**)&h2h, g_h2h); cudaGetSymbolAddress((void**)&h2l, g_h2l);
    cudaGetSymbolAddress((void**)&uh,  g_uh);  cudaGetSymbolAddress((void**)&ul,  g_ul);
    cudaGetSymbolAddress((void**)&wqh, g_wqh); cudaGetSymbolAddress((void**)&wql, g_wql);
    cudaGetSymbolAddress((void**)&wph, g_wph); cudaGetSymbolAddress((void**)&wpl, g_wpl);
    cudaGetSymbolAddress((void**)&wfh, g_wfh); cudaGetSymbolAddress((void**)&wfl, g_wfl);
    cudaGetSymbolAddress((void**)&wmh, g_wmh); cudaGetSymbolAddress((void**)&wml, g_wml);

    cudaFuncSetAttribute(attn_kernel,
        cudaFuncAttributeMaxDynamicSharedMemorySize, (int)ATTN_SMEM);

    // weight transpose + split (per launch; ~15us total)
    tsplit_kernel<<<dim3(C3_DIM / 32, C_DIM / 32), 256>>>(w_attn, wqh, wql, C_DIM, C3_DIM);
    tsplit_kernel<<<dim3(C_DIM / 32, C_DIM / 32), 256>>>(w_attn_proj, wph, wpl, C_DIM, C_DIM);
    tsplit_kernel<<<dim3(C4_DIM / 32, C_DIM / 32), 256>>>(w_fc, wfh, wfl, C_DIM, C4_DIM);
    tsplit_kernel<<<dim3(C_DIM / 32, C4_DIM / 32), 256>>>(w_mlp_proj, wmh, wml, C4_DIM, C_DIM);

    // 1. LN1 -> bf16 hi/lo
    ln_split_kernel<<<M_ROWS, 256>>>(x, ln1_g, ln1_b, hh, hl);
    // 2. qkv = h @ w_attn + b    (f32 out)
    mm_kernel<0><<<dim3(C3_DIM / 128, M_ROWS / 128), 256>>>(
        hh, hl, wqh, wql, b_attn, nullptr, qkv, nullptr, nullptr,
        M_ROWS, C3_DIM, C_DIM);
    // 3. attention -> y hi/lo
    attn_kernel<<<dim3(T_SEQ / 64, N_HEAD, 2), 256, ATTN_SMEM>>>(qkv, yh, yl);
    // 4. x1 = x + y @ w_attn_proj + b
    mm_kernel<1><<<dim3(C_DIM / 128, M_ROWS / 128), 256>>>(
        yh, yl, wph, wpl, b_attn_proj, x, x1, nullptr, nullptr,
        M_ROWS, C_DIM, C_DIM);
    // 5. LN2 -> bf16 hi/lo
    ln_split_kernel<<<M_ROWS, 256>>>(x1, ln2_g, ln2_b, h2h, h2l);
    // 6. u = gelu(h2 @ w_fc + b) -> bf16 hi/lo
    mm_kernel<2><<<dim3(C4_DIM / 128, M_ROWS / 128), 256>>>(
        h2h, h2l, wfh, wfl, b_fc, nullptr, nullptr, uh, ul,
        M_ROWS, C4_DIM, C_DIM);
    // 7. out = x1 + u @ w_mlp_proj + b
    mm_kernel<3><<<dim3(C_DIM / 128, M_ROWS / 128), 256>>>(
        uh, ul, wmh, wml, b_mlp_proj, x1, out, nullptr, nullptr,
        M_ROWS, C_DIM, C4_DIM);
}

// round 9
// speedup vs baseline: 4.8791x; 1.3275x over previous
#include <cuda_runtime.h>
#include <cuda_bf16.h>
#include <math.h>
#include <stdint.h>

// ---------------------------------------------------------------------------
// GPT-2 transformer block. GEMMs + attention on mma.sync bf16 (hi/lo split).
// B=2, T=2048, C=768, H=12, hd=64.  M = B*T = 4096.
// ---------------------------------------------------------------------------

#define M_ROWS 4096
#define C_DIM  768
#define C3_DIM 2304
#define C4_DIM 3072
#define N_HEAD 12
#define HD     64
#define T_SEQ  2048

// ---------------- scratch (device globals) ----------------
__device__ float g_qkv[M_ROWS * C3_DIM];
__device__ float g_x1 [M_ROWS * C_DIM];
__device__ __nv_bfloat16 g_hh [M_ROWS * C_DIM],  g_hl [M_ROWS * C_DIM];
__device__ __nv_bfloat16 g_yh [M_ROWS * C_DIM],  g_yl [M_ROWS * C_DIM];
__device__ __nv_bfloat16 g_h2h[M_ROWS * C_DIM],  g_h2l[M_ROWS * C_DIM];
__device__ __nv_bfloat16 g_uh [M_ROWS * C4_DIM], g_ul [M_ROWS * C4_DIM];
__device__ __nv_bfloat16 g_wqh[C3_DIM * C_DIM],  g_wql[C3_DIM * C_DIM];
__device__ __nv_bfloat16 g_wph[C_DIM * C_DIM],   g_wpl[C_DIM * C_DIM];
__device__ __nv_bfloat16 g_wfh[C4_DIM * C_DIM],  g_wfl[C4_DIM * C_DIM];
__device__ __nv_bfloat16 g_wmh[C_DIM * C4_DIM],  g_wml[C_DIM * C4_DIM];

// ---------------- PTX helpers (base ISA only) ----------
__device__ __forceinline__ uint32_t smem_u32(const void* p) {
    uint32_t a;
    asm("{ .reg .u64 t; cvta.to.shared.u64 t, %1; cvt.u32.u64 %0, t; }"
        : "=r"(a) : "l"(p));
    return a;
}

#define CPA16(dst, src) \
    asm volatile("cp.async.cg.shared.global [%0], [%1], 16;" :: "r"(dst), "l"(src))
#define CP_COMMIT() asm volatile("cp.async.commit_group;" ::: "memory")
#define CP_WAIT1()  asm volatile("cp.async.wait_group 1;" ::: "memory")
#define CP_WAIT0()  asm volatile("cp.async.wait_group 0;" ::: "memory")

#define LDSM_X4(r, addr)                                                       \
    asm volatile("ldmatrix.sync.aligned.m8n8.x4.shared.b16 {%0,%1,%2,%3}, [%4];" \
        : "=r"((r)[0]), "=r"((r)[1]), "=r"((r)[2]), "=r"((r)[3]) : "r"(addr))

#define LDSM_X4_T(r, addr)                                                     \
    asm volatile("ldmatrix.sync.aligned.m8n8.x4.trans.shared.b16 {%0,%1,%2,%3}, [%4];" \
        : "=r"((r)[0]), "=r"((r)[1]), "=r"((r)[2]), "=r"((r)[3]) : "r"(addr))

#define MMA_BF16(d, a, b)                                                      \
    asm volatile("mma.sync.aligned.m16n8k16.row.col.f32.bf16.bf16.f32 "        \
        "{%0,%1,%2,%3}, {%4,%5,%6,%7}, {%8,%9}, {%0,%1,%2,%3};"                \
        : "+f"((d)[0]), "+f"((d)[1]), "+f"((d)[2]), "+f"((d)[3])               \
        : "r"((a)[0]), "r"((a)[1]), "r"((a)[2]), "r"((a)[3]),                  \
          "r"((b)[0]), "r"((b)[1]))

__device__ __forceinline__ float gelu_f(float v) {
    const float c = 0.7978845608028654f;
    return 0.5f * v * (1.0f + tanhf(c * (v + 0.044715f * v * v * v)));
}
__device__ __forceinline__ void split_bf16(float v, __nv_bfloat16& hi, __nv_bfloat16& lo) {
    hi = __float2bfloat16(v);
    lo = __float2bfloat16(v - __bfloat162float(hi));
}
// pack two floats into bf16x2 hi-frag and lo-frag words
__device__ __forceinline__ void p2frag(float a, float b, uint32_t& hi, uint32_t& lo) {
    __nv_bfloat16 ha = __float2bfloat16(a), hb = __float2bfloat16(b);
    __nv_bfloat16 la = __float2bfloat16(a - __bfloat162float(ha));
    __nv_bfloat16 lb = __float2bfloat16(b - __bfloat162float(hb));
    __nv_bfloat162 H(ha, hb), L(la, lb);
    hi = *(uint32_t*)&H; lo = *(uint32_t*)&L;
}
__device__ __forceinline__ void store_split2(
    __nv_bfloat16* Hp, __nv_bfloat16* Lp, int idx, float a, float b) {
    __nv_bfloat16 ha, la, hb, lb;
    split_bf16(a, ha, la); split_bf16(b, hb, lb);
    *(__nv_bfloat162*)(Hp + idx) = __nv_bfloat162(ha, hb);
    *(__nv_bfloat162*)(Lp + idx) = __nv_bfloat162(la, lb);
}

// ---------------------------------------------------------------------------
// mma.sync GEMM (unchanged from round 6, passing at rel_err 7e-6)
// ---------------------------------------------------------------------------
template <int EP>
__global__ __launch_bounds__(256)
void mm_kernel(const __nv_bfloat16* __restrict__ Ah, const __nv_bfloat16* __restrict__ Al,
               const __nv_bfloat16* __restrict__ Bh, const __nv_bfloat16* __restrict__ Bl,
               const float* __restrict__ bias, const float* __restrict__ res,
               float* __restrict__ outF,
               __nv_bfloat16* __restrict__ outH, __nv_bfloat16* __restrict__ outL,
               int M, int N, int K)
{
    __shared__ __nv_bfloat16 Asm[2][128][40];
    __shared__ __nv_bfloat16 Bsm[2][128][40];

    int tid = threadIdx.x;
    int wid = tid >> 5, lane = tid & 31;
    int wm = wid & 3, wn = wid >> 2;
    int bm = blockIdx.y, bn = blockIdx.x;

    const int KC  = K / 32;
    const int NIT = 3 * KC;

    uint32_t sA[2] = { smem_u32(&Asm[0][0][0]), smem_u32(&Asm[1][0][0]) };
    uint32_t sB[2] = { smem_u32(&Bsm[0][0][0]), smem_u32(&Bsm[1][0][0]) };

    auto load_chunk = [&](int it2, int b2) {
        int term = it2 / KC;
        int k0 = (it2 - term * KC) * 32;
        const __nv_bfloat16* Ag = (term == 2) ? Al : Ah;
        const __nv_bfloat16* Bg = (term == 1) ? Bl : Bh;
        #pragma unroll
        for (int i = 0; i < 2; i++) {
            int s = tid + i * 256;
            int r = s >> 2, c = s & 3;
            CPA16(sA[b2] + r * 80 + c * 16,
                  (const char*)(Ag + (size_t)(bm * 128 + r) * K + k0) + c * 16);
            CPA16(sB[b2] + r * 80 + c * 16,
                  (const char*)(Bg + (size_t)(bn * 128 + r) * K + k0) + c * 16);
        }
    };

    float acc[2][8][4];
    #pragma unroll
    for (int i = 0; i < 2; i++)
        #pragma unroll
        for (int j = 0; j < 8; j++)
            #pragma unroll
            for (int q = 0; q < 4; q++) acc[i][j][q] = 0.f;

    load_chunk(0, 0); CP_COMMIT();
    load_chunk(1, 1); CP_COMMIT();

    int mrow = (lane & 7) + ((lane >> 3) & 1) * 8;
    int kgrp = (lane >> 4) * 8;

    for (int it = 0; it < NIT; ++it) {
        int b = it & 1;
        if (it + 1 < NIT) CP_WAIT1(); else CP_WAIT0();
        __syncthreads();

        #pragma unroll
        for (int ks = 0; ks < 2; ks++) {
            int kcol = ks * 16 + kgrp;
            uint32_t af[2][4], bf[4][4];
            #pragma unroll
            for (int mt = 0; mt < 2; mt++)
                LDSM_X4(af[mt], sA[b] + (wm * 32 + mt * 16 + mrow) * 80 + kcol * 2);
            #pragma unroll
            for (int np = 0; np < 4; np++)
                LDSM_X4(bf[np], sB[b] + (wn * 64 + np * 16 + mrow) * 80 + kcol * 2);
            #pragma unroll
            for (int mt = 0; mt < 2; mt++)
                #pragma unroll
                for (int nt = 0; nt < 8; nt++) {
                    uint32_t bb[2] = { bf[nt >> 1][nt & 1], bf[nt >> 1][(nt & 1) + 2] };
                    MMA_BF16(acc[mt][nt], af[mt], bb);
                }
        }
        __syncthreads();
        if (it + 2 < NIT) { load_chunk(it + 2, b); CP_COMMIT(); }
    }

    #pragma unroll
    for (int mt = 0; mt < 2; mt++) {
        int gr0 = bm * 128 + wm * 32 + mt * 16 + (lane >> 2);
        #pragma unroll
        for (int nt = 0; nt < 8; nt++) {
            int gc = bn * 128 + wn * 64 + nt * 8 + (lane & 3) * 2;
            float2 bi = *(const float2*)(bias + gc);
            #pragma unroll
            for (int h = 0; h < 2; h++) {
                int gr = gr0 + h * 8;
                float v0 = acc[mt][nt][h * 2 + 0] + bi.x;
                float v1 = acc[mt][nt][h * 2 + 1] + bi.y;
                size_t o = (size_t)gr * N + gc;
                if (EP == 1 || EP == 3) {
                    float2 rr = *(const float2*)(res + o);
                    v0 += rr.x; v1 += rr.y;
                }
                if (EP == 2) {
                    v0 = gelu_f(v0); v1 = gelu_f(v1);
                    __nv_bfloat16 h0, h1, l0, l1;
                    split_bf16(v0, h0, l0); split_bf16(v1, h1, l1);
                    *(__nv_bfloat162*)(outH + o) = __nv_bfloat162(h0, h1);
                    *(__nv_bfloat162*)(outL + o) = __nv_bfloat162(l0, l1);
                } else {
                    float2 ov = {v0, v1};
                    *(float2*)(outF + o) = ov;
                }
            }
        }
    }
}

// ---------------------------------------------------------------------------
// Transpose + hi/lo split:  w[K,N] f32 -> th/tl [N,K] bf16
// ---------------------------------------------------------------------------
__global__ __launch_bounds__(256) void tsplit_kernel(
    const float* __restrict__ w, __nv_bfloat16* __restrict__ th,
    __nv_bfloat16* __restrict__ tl, int K, int N)
{
    __shared__ float t[32][33];
    int n0 = blockIdx.x * 32, k0 = blockIdx.y * 32;
    int tx = threadIdx.x & 31, ty = threadIdx.x >> 5;
    #pragma unroll
    for (int j = 0; j < 4; j++) {
        int k = ty + j * 8;
        t[k][tx] = w[(size_t)(k0 + k) * N + n0 + tx];
    }
    __syncthreads();
    #pragma unroll
    for (int j = 0; j < 4; j++) {
        int nn = ty + j * 8;
        float v = t[tx][nn];
        __nv_bfloat16 hi, lo;
        split_bf16(v, hi, lo);
        size_t o = (size_t)(n0 + nn) * K + k0 + tx;
        th[o] = hi; tl[o] = lo;
    }
}

// ---------------------------------------------------------------------------
// LayerNorm -> bf16 hi/lo
// ---------------------------------------------------------------------------
__global__ __launch_bounds__(256) void ln_split_kernel(
    const float* __restrict__ x, const float* __restrict__ g,
    const float* __restrict__ b, __nv_bfloat16* __restrict__ oh,
    __nv_bfloat16* __restrict__ ol)
{
    int row = blockIdx.x;
    int tid = threadIdx.x;
    const float* xr = x + (size_t)row * C_DIM;

    float v0 = xr[tid], v1 = xr[tid + 256], v2 = xr[tid + 512];
    float s = v0 + v1 + v2;
    float sq = v0 * v0 + v1 * v1 + v2 * v2;
    #pragma unroll
    for (int o = 16; o > 0; o >>= 1) {
        s  += __shfl_xor_sync(0xffffffffu, s,  o);
        sq += __shfl_xor_sync(0xffffffffu, sq, o);
    }
    __shared__ float ss[8], sqs[8];
    int wid = tid >> 5, lane = tid & 31;
    if (lane == 0) { ss[wid] = s; sqs[wid] = sq; }
    __syncthreads();
    s = 0.f; sq = 0.f;
    #pragma unroll
    for (int i = 0; i < 8; i++) { s += ss[i]; sq += sqs[i]; }

    float mu = s * (1.0f / C_DIM);
    float var = sq * (1.0f / C_DIM) - mu * mu;
    float inv = rsqrtf(var + 1e-5f);

    size_t base = (size_t)row * C_DIM;
    #pragma unroll
    for (int e = 0; e < 3; e++) {
        int idx = tid + e * 256;
        float val = ((e == 0 ? v0 : e == 1 ? v1 : v2) - mu) * inv * g[idx] + b[idx];
        __nv_bfloat16 hi, lo;
        split_bf16(val, hi, lo);
        oh[base + idx] = hi; ol[base + idx] = lo;
    }
}

// ---------------------------------------------------------------------------
// Flash attention on mma.sync bf16, hi/lo split (3 terms for S and for PV).
// CTA: 128 queries x one (head, batch). 8 warps, each 16 query rows.
// K-tiles of 64 keys. Q pre-scaled by 1/8. smem stride 72 bf16.
// ---------------------------------------------------------------------------
#define ASTR 72
#define ATTN_SMEM2 (size_t)((2 * 128 * ASTR + 4 * 64 * ASTR) * sizeof(__nv_bfloat16))

__global__ __launch_bounds__(256) void attn_mma_kernel(
    const float* __restrict__ qkv,
    __nv_bfloat16* __restrict__ yh, __nv_bfloat16* __restrict__ yl)
{
    extern __shared__ __nv_bfloat16 smb[];
    __nv_bfloat16* Qh = smb;
    __nv_bfloat16* Ql = Qh + 128 * ASTR;
    __nv_bfloat16* Kh = Ql + 128 * ASTR;
    __nv_bfloat16* Kl = Kh + 64 * ASTR;
    __nv_bfloat16* Vh = Kl + 64 * ASTR;
    __nv_bfloat16* Vl = Vh + 64 * ASTR;

    int qt = gridDim.x - 1 - blockIdx.x;   // heavy tiles first
    int hh = blockIdx.y, bb = blockIdx.z;
    int tid = threadIdx.x, wid = tid >> 5, lane = tid & 31;

    uint32_t sQh = smem_u32(Qh), sQl = smem_u32(Ql);
    uint32_t sKh = smem_u32(Kh), sKl = smem_u32(Kl);
    uint32_t sVh = smem_u32(Vh), sVl = smem_u32(Vl);

    int mrow = (lane & 7) + ((lane >> 3) & 1) * 8;
    int kgrp = (lane >> 4) * 8;

    // ---- load Q tile (scaled by 1/8), split hi/lo ----
    #pragma unroll
    for (int p = tid; p < 2048; p += 256) {
        int r = p >> 4, c4 = (p & 15) << 2;
        float4 v = *(const float4*)(qkv +
            ((size_t)(bb * T_SEQ + qt * 128 + r)) * C3_DIM + hh * HD + c4);
        store_split2(Qh, Ql, r * ASTR + c4,     v.x * 0.125f, v.y * 0.125f);
        store_split2(Qh, Ql, r * ASTR + c4 + 2, v.z * 0.125f, v.w * 0.125f);
    }

    float m0 = -1e30f, m1 = -1e30f, l0 = 0.f, l1 = 0.f;
    float oacc[8][4];
    #pragma unroll
    for (int i = 0; i < 8; i++)
        #pragma unroll
        for (int j = 0; j < 4; j++) oacc[i][j] = 0.f;

    int nkt = 2 * qt + 2;
    for (int kt = 0; kt < nkt; kt++) {
        __syncthreads();
        // ---- load K/V tile (64x64), split hi/lo ----
        #pragma unroll
        for (int p = tid; p < 1024; p += 256) {
            int r = p >> 4, c4 = (p & 15) << 2;
            size_t gk = ((size_t)(bb * T_SEQ + kt * 64 + r)) * C3_DIM
                        + C_DIM + hh * HD + c4;
            float4 kv = *(const float4*)(qkv + gk);
            float4 vv = *(const float4*)(qkv + gk + C_DIM);
            store_split2(Kh, Kl, r * ASTR + c4,     kv.x, kv.y);
            store_split2(Kh, Kl, r * ASTR + c4 + 2, kv.z, kv.w);
            store_split2(Vh, Vl, r * ASTR + c4,     vv.x, vv.y);
            store_split2(Vh, Vl, r * ASTR + c4 + 2, vv.z, vv.w);
        }
        __syncthreads();

        // ---- S = Q @ K^T  (3 hi/lo terms) ----
        float sacc[8][4];
        #pragma unroll
        for (int i = 0; i < 8; i++)
            #pragma unroll
            for (int j = 0; j < 4; j++) sacc[i][j] = 0.f;

        #pragma unroll
        for (int kc = 0; kc < 4; kc++) {
            uint32_t aqh[4], aql[4];
            uint32_t aoff = ((wid * 16 + mrow) * ASTR + kc * 16 + kgrp) * 2;
            LDSM_X4(aqh, sQh + aoff);
            LDSM_X4(aql, sQl + aoff);
            #pragma unroll
            for (int ng = 0; ng < 4; ng++) {
                uint32_t bh[4], bl[4];
                uint32_t boff = ((ng * 16 + mrow) * ASTR + kc * 16 + kgrp) * 2;
                LDSM_X4(bh, sKh + boff);
                LDSM_X4(bl, sKl + boff);
                #pragma unroll
                for (int t = 0; t < 2; t++) {
                    uint32_t b0[2] = { bh[t], bh[t + 2] };
                    uint32_t b1[2] = { bl[t], bl[t + 2] };
                    MMA_BF16(sacc[ng * 2 + t], aqh, b0);
                    MMA_BF16(sacc[ng * 2 + t], aqh, b1);
                    MMA_BF16(sacc[ng * 2 + t], aql, b0);
                }
            }
        }

        // ---- causal mask (only tiles overlapping the diagonal) ----
        int g0 = qt * 128 + wid * 16 + (lane >> 2);
        if (kt * 64 + 63 > qt * 128 + wid * 16) {
            #pragma unroll
            for (int nt = 0; nt < 8; nt++) {
                int kc0 = kt * 64 + nt * 8 + (lane & 3) * 2;
                if (kc0     > g0)     sacc[nt][0] = -1e30f;
                if (kc0 + 1 > g0)     sacc[nt][1] = -1e30f;
                if (kc0     > g0 + 8) sacc[nt][2] = -1e30f;
                if (kc0 + 1 > g0 + 8) sacc[nt][3] = -1e30f;
            }
        }

        // ---- online softmax (register resident) ----
        float mt0 = -1e30f, mt1 = -1e30f;
        #pragma unroll
        for (int nt = 0; nt < 8; nt++) {
            mt0 = fmaxf(mt0, fmaxf(sacc[nt][0], sacc[nt][1]));
            mt1 = fmaxf(mt1, fmaxf(sacc[nt][2], sacc[nt][3]));
        }
        mt0 = fmaxf(mt0, __shfl_xor_sync(0xffffffffu, mt0, 1));
        mt0 = fmaxf(mt0, __shfl_xor_sync(0xffffffffu, mt0, 2));
        mt1 = fmaxf(mt1, __shfl_xor_sync(0xffffffffu, mt1, 1));
        mt1 = fmaxf(mt1, __shfl_xor_sync(0xffffffffu, mt1, 2));

        float mn0 = fmaxf(m0, mt0), mn1 = fmaxf(m1, mt1);
        float c0 = __expf(m0 - mn0), c1 = __expf(m1 - mn1);
        m0 = mn0; m1 = mn1;

        float ps0 = 0.f, ps1 = 0.f;
        #pragma unroll
        for (int nt = 0; nt < 8; nt++) {
            sacc[nt][0] = __expf(sacc[nt][0] - m0);
            sacc[nt][1] = __expf(sacc[nt][1] - m0);
            sacc[nt][2] = __expf(sacc[nt][2] - m1);
            sacc[nt][3] = __expf(sacc[nt][3] - m1);
            ps0 += sacc[nt][0] + sacc[nt][1];
            ps1 += sacc[nt][2] + sacc[nt][3];
        }
        ps0 += __shfl_xor_sync(0xffffffffu, ps0, 1);
        ps0 += __shfl_xor_sync(0xffffffffu, ps0, 2);
        ps1 += __shfl_xor_sync(0xffffffffu, ps1, 1);
        ps1 += __shfl_xor_sync(0xffffffffu, ps1, 2);
        l0 = l0 * c0 + ps0;
        l1 = l1 * c1 + ps1;
        #pragma unroll
        for (int dt = 0; dt < 8; dt++) {
            oacc[dt][0] *= c0; oacc[dt][1] *= c0;
            oacc[dt][2] *= c1; oacc[dt][3] *= c1;
        }

        // ---- O += P @ V (3 hi/lo terms); P frags built in-register ----
        #pragma unroll
        for (int kc = 0; kc < 4; kc++) {
            uint32_t ah[4], al[4];
            p2frag(sacc[2 * kc][0],     sacc[2 * kc][1],     ah[0], al[0]);
            p2frag(sacc[2 * kc][2],     sacc[2 * kc][3],     ah[1], al[1]);
            p2frag(sacc[2 * kc + 1][0], sacc[2 * kc + 1][1], ah[2], al[2]);
            p2frag(sacc[2 * kc + 1][2], sacc[2 * kc + 1][3], ah[3], al[3]);
            #pragma unroll
            for (int ng = 0; ng < 4; ng++) {
                uint32_t bvh[4], bvl[4];
                uint32_t voff = ((kc * 16 + ((lane >> 3) & 1) * 8 + (lane & 7)) * ASTR
                                 + ng * 16 + (lane >> 4) * 8) * 2;
                LDSM_X4_T(bvh, sVh + voff);
                LDSM_X4_T(bvl, sVl + voff);
                #pragma unroll
                for (int t = 0; t < 2; t++) {
                    int dt = ng * 2 + t;
                    uint32_t b0[2] = { bvh[2 * t], bvh[2 * t + 1] };
                    uint32_t b1[2] = { bvl[2 * t], bvl[2 * t + 1] };
                    MMA_BF16(oacc[dt], ah, b0);
                    MMA_BF16(oacc[dt], ah, b1);
                    MMA_BF16(oacc[dt], al, b0);
                }
            }
        }
    }

    // ---- epilogue: normalize, split hi/lo, store ----
    float i0 = 1.0f / l0, i1 = 1.0f / l1;
    int gr0 = qt * 128 + wid * 16 + (lane >> 2);
    #pragma unroll
    for (int dt = 0; dt < 8; dt++) {
        int col = hh * HD + dt * 8 + (lane & 3) * 2;
        size_t o0 = ((size_t)(bb * T_SEQ + gr0)) * C_DIM + col;
        size_t o1 = ((size_t)(bb * T_SEQ + gr0 + 8)) * C_DIM + col;
        __nv_bfloat16 ha, la, hb, lb;
        split_bf16(oacc[dt][0] * i0, ha, la);
        split_bf16(oacc[dt][1] * i0, hb, lb);
        *(__nv_bfloat162*)(yh + o0) = __nv_bfloat162(ha, hb);
        *(__nv_bfloat162*)(yl + o0) = __nv_bfloat162(la, lb);
        split_bf16(oacc[dt][2] * i1, ha, la);
        split_bf16(oacc[dt][3] * i1, hb, lb);
        *(__nv_bfloat162*)(yh + o1) = __nv_bfloat162(ha, hb);
        *(__nv_bfloat162*)(yl + o1) = __nv_bfloat162(la, lb);
    }
}

// ---------------------------------------------------------------------------
// Launch
// ---------------------------------------------------------------------------
extern "C" void kernel_launch(void* const* d_in, const int* in_sizes, int n_in,
                              void* d_out, int out_size)
{
    const float* x           = (const float*)d_in[0];
    const float* ln1_g       = (const float*)d_in[1];
    const float* ln1_b       = (const float*)d_in[2];
    const float* w_attn      = (const float*)d_in[3];
    const float* b_attn      = (const float*)d_in[4];
    const float* w_attn_proj = (const float*)d_in[5];
    const float* b_attn_proj = (const float*)d_in[6];
    const float* ln2_g       = (const float*)d_in[7];
    const float* ln2_b       = (const float*)d_in[8];
    const float* w_fc        = (const float*)d_in[9];
    const float* b_fc        = (const float*)d_in[10];
    const float* w_mlp_proj  = (const float*)d_in[11];
    const float* b_mlp_proj  = (const float*)d_in[12];
    float* out = (float*)d_out;

    float *qkv, *x1;
    __nv_bfloat16 *hh, *hl, *yh, *yl, *h2h, *h2l, *uh, *ul;
    __nv_bfloat16 *wqh, *wql, *wph, *wpl, *wfh, *wfl, *wmh, *wml;
    cudaGetSymbolAddress((void**)&qkv, g_qkv);
    cudaGetSymbolAddress((void**)&x1,  g_x1);
    cudaGetSymbolAddress((void**)&hh,  g_hh);  cudaGetSymbolAddress((void**)&hl,  g_hl);
    cudaGetSymbolAddress((void**)&yh,  g_yh);  cudaGetSymbolAddress((void**)&yl,  g_yl);
    cudaGetSymbolAddress((void**)&h2h, g_h2h); cudaGetSymbolAddress((void**)&h2l, g_h2l);
    cudaGetSymbolAddress((void**)&uh,  g_uh);  cudaGetSymbolAddress((void**)&ul,  g_ul);
    cudaGetSymbolAddress((void**)&wqh, g_wqh); cudaGetSymbolAddress((void**)&wql, g_wql);
    cudaGetSymbolAddress((void**)&wph, g_wph); cudaGetSymbolAddress((void**)&wpl, g_wpl);
    cudaGetSymbolAddress((void**)&wfh, g_wfh); cudaGetSymbolAddress((void**)&wfl, g_wfl);
    cudaGetSymbolAddress((void**)&wmh, g_wmh); cudaGetSymbolAddress((void**)&wml, g_wml);

    cudaFuncSetAttribute(attn_mma_kernel,
        cudaFuncAttributeMaxDynamicSharedMemorySize, (int)ATTN_SMEM2);

    // weight transpose + split
    tsplit_kernel<<<dim3(C3_DIM / 32, C_DIM / 32), 256>>>(w_attn, wqh, wql, C_DIM, C3_DIM);
    tsplit_kernel<<<dim3(C_DIM / 32, C_DIM / 32), 256>>>(w_attn_proj, wph, wpl, C_DIM, C_DIM);
    tsplit_kernel<<<dim3(C4_DIM / 32, C_DIM / 32), 256>>>(w_fc, wfh, wfl, C_DIM, C4_DIM);
    tsplit_kernel<<<dim3(C_DIM / 32, C4_DIM / 32), 256>>>(w_mlp_proj, wmh, wml, C4_DIM, C_DIM);

    // 1. LN1 -> bf16 hi/lo
    ln_split_kernel<<<M_ROWS, 256>>>(x, ln1_g, ln1_b, hh, hl);
    // 2. qkv = h @ w_attn + b
    mm_kernel<0><<<dim3(C3_DIM / 128, M_ROWS / 128), 256>>>(
        hh, hl, wqh, wql, b_attn, nullptr, qkv, nullptr, nullptr,
        M_ROWS, C3_DIM, C_DIM);
    // 3. attention (tensor-core flash) -> y hi/lo
    attn_mma_kernel<<<dim3(T_SEQ / 128, N_HEAD, 2), 256, ATTN_SMEM2>>>(qkv, yh, yl);
    // 4. x1 = x + y @ w_attn_proj + b
    mm_kernel<1><<<dim3(C_DIM / 128, M_ROWS / 128), 256>>>(
        yh, yl, wph, wpl, b_attn_proj, x, x1, nullptr, nullptr,
        M_ROWS, C_DIM, C_DIM);
    // 5. LN2 -> bf16 hi/lo
    ln_split_kernel<<<M_ROWS, 256>>>(x1, ln2_g, ln2_b, h2h, h2l);
    // 6. u = gelu(h2 @ w_fc + b) -> bf16 hi/lo
    mm_kernel<2><<<dim3(C4_DIM / 128, M_ROWS / 128), 256>>>(
        h2h, h2l, wfh, wfl, b_fc, nullptr, nullptr, uh, ul,
        M_ROWS, C4_DIM, C_DIM);
    // 7. out = x1 + u @ w_mlp_proj + b
    mm_kernel<3><<<dim3(C_DIM / 128, M_ROWS / 128), 256>>>(
        uh, ul, wmh, wml, b_mlp_proj, x1, out, nullptr, nullptr,
        M_ROWS, C_DIM, C4_DIM);
}